// round 2
// baseline (speedup 1.0000x reference)
#include <cuda_runtime.h>
#include <math.h>

#define B_SZ   2
#define T_SEQ  2048
#define C_DIM  1024
#define NH     16
#define HD     64
#define M_ROWS (B_SZ * T_SEQ)   /* 4096 */
#define N_QKV  (3 * C_DIM)      /* 3072 */

// Scratch (allocation-free rule: __device__ globals)
__device__ float g_q[(size_t)B_SZ * NH * T_SEQ * HD];
__device__ float g_k[(size_t)B_SZ * NH * T_SEQ * HD];
__device__ float g_v[(size_t)B_SZ * NH * T_SEQ * HD];
__device__ float g_y[(size_t)M_ROWS * C_DIM];

// ---------------------------------------------------------------------------
// QKV GEMM: X[4096,1024] @ W[1024,3072] + b  -> scatter into g_q/g_k/g_v
// 128x128 tile, Ktile=8, 256 threads, 8x8 per thread. Q pre-scaled by 0.125.
// ---------------------------------------------------------------------------
__global__ __launch_bounds__(256) void qkv_gemm_kernel(
    const float* __restrict__ X, const float* __restrict__ W,
    const float* __restrict__ bias)
{
    const int K = C_DIM, N = N_QKV;
    __shared__ float As[8][128];
    __shared__ float Bs[8][128];

    int tid = threadIdx.x;
    int ty  = tid >> 4, tx = tid & 15;
    int row0 = blockIdx.y * 128, col0 = blockIdx.x * 128;

    int a_row = tid >> 1;            // 0..127
    int a_col = (tid & 1) << 2;      // 0 or 4
    int b_row = tid >> 5;            // 0..7
    int b_col = (tid & 31) << 2;     // 0..124

    const float* Aptr = X + (size_t)(row0 + a_row) * K + a_col;
    const float* Bptr = W + (size_t)b_row * N + col0 + b_col;

    float acc[8][8];
    #pragma unroll
    for (int i = 0; i < 8; i++)
        #pragma unroll
        for (int j = 0; j < 8; j++) acc[i][j] = 0.f;

    for (int k0 = 0; k0 < K; k0 += 8) {
        float4 av = *(const float4*)(Aptr + k0);
        float4 bv = *(const float4*)(Bptr + (size_t)k0 * N);
        As[a_col + 0][a_row] = av.x;
        As[a_col + 1][a_row] = av.y;
        As[a_col + 2][a_row] = av.z;
        As[a_col + 3][a_row] = av.w;
        *(float4*)&Bs[b_row][b_col] = bv;
        __syncthreads();

        #pragma unroll
        for (int kk = 0; kk < 8; kk++) {
            float4 a0 = *(const float4*)&As[kk][ty * 8];
            float4 a1 = *(const float4*)&As[kk][ty * 8 + 4];
            float4 b0 = *(const float4*)&Bs[kk][tx * 8];
            float4 b1 = *(const float4*)&Bs[kk][tx * 8 + 4];
            float ar[8] = {a0.x, a0.y, a0.z, a0.w, a1.x, a1.y, a1.z, a1.w};
            float br[8] = {b0.x, b0.y, b0.z, b0.w, b1.x, b1.y, b1.z, b1.w};
            #pragma unroll
            for (int i = 0; i < 8; i++)
                #pragma unroll
                for (int j = 0; j < 8; j++)
                    acc[i][j] += ar[i] * br[j];
        }
        __syncthreads();
    }

    // Epilogue: bias + scatter to [B,H,T,D] layout. Q scaled by 1/sqrt(64).
    #pragma unroll
    for (int i = 0; i < 8; i++) {
        int r  = row0 + ty * 8 + i;
        int bb = r >> 11;            // batch
        int t  = r & 2047;           // time
        #pragma unroll
        for (int j = 0; j < 8; j++) {
            int jc = col0 + tx * 8 + j;
            float val = acc[i][j] + bias[jc];
            int part = jc >> 10;     // 0=q 1=k 2=v
            int cc   = jc & 1023;
            int h    = cc >> 6;
            int d    = cc & 63;
            size_t idx = (((size_t)(bb * NH + h)) * T_SEQ + t) * HD + d;
            if (part == 0)       g_q[idx] = val * 0.125f;
            else if (part == 1)  g_k[idx] = val;
            else                 g_v[idx] = val;
        }
    }
}

// ---------------------------------------------------------------------------
// Flash attention, fp32, causal. One block = one (b,h) x one 64-row Q tile.
// 256 threads: thread (ty,tx) owns rows 4ty..4ty+3 and cols 4tx..4tx+3.
// K tile XOR-swizzled in smem to keep K-major float4 reads ~conflict-free.
// ---------------------------------------------------------------------------
__global__ __launch_bounds__(256) void attn_kernel()
{
    extern __shared__ float sm[];
    float* Qs = sm;             // 64*64
    float* Ks = sm + 4096;      // 64*64 (swizzled)
    float* Vs = sm + 8192;      // 64*64
    float* Ps = sm + 12288;     // 64*64

    int qt = blockIdx.x;        // q tile 0..31
    int bh = blockIdx.y;        // 0..31
    int b  = bh >> 4, h = bh & 15;
    const float* qbase = g_q + (size_t)bh * T_SEQ * HD + (size_t)qt * 64 * HD;
    const float* kbase = g_k + (size_t)bh * T_SEQ * HD;
    const float* vbase = g_v + (size_t)bh * T_SEQ * HD;

    int tid = threadIdx.x;
    int ty  = tid >> 4, tx = tid & 15;

    // Load Q tile (already scaled)
    #pragma unroll
    for (int p = 0; p < 4; p++) {
        int e  = p * 256 + tid;
        int m  = e >> 4;
        int d4 = (e & 15) << 2;
        *(float4*)&Qs[m * 64 + d4] = *(const float4*)(qbase + m * HD + d4);
    }

    float m_i[4], l_i[4], o[4][4];
    #pragma unroll
    for (int i = 0; i < 4; i++) {
        m_i[i] = -1e30f; l_i[i] = 0.f;
        #pragma unroll
        for (int j = 0; j < 4; j++) o[i][j] = 0.f;
    }

    for (int kt = 0; kt <= qt; kt++) {
        // Load K (swizzled) and V tiles
        #pragma unroll
        for (int p = 0; p < 4; p++) {
            int e  = p * 256 + tid;
            int n  = e >> 4;
            int d4 = (e & 15) << 2;
            int sw = d4 ^ (((n >> 2) & 7) << 3);
            size_t gofs = (size_t)(kt * 64 + n) * HD + d4;
            *(float4*)&Ks[n * 64 + sw] = *(const float4*)(kbase + gofs);
            *(float4*)&Vs[n * 64 + d4] = *(const float4*)(vbase + gofs);
        }
        __syncthreads();

        // S = Q K^T (64x64), 4x4 per thread
        float s[4][4];
        #pragma unroll
        for (int i = 0; i < 4; i++)
            #pragma unroll
            for (int j = 0; j < 4; j++) s[i][j] = 0.f;

        #pragma unroll
        for (int d4 = 0; d4 < 64; d4 += 4) {
            float4 q4[4], k4[4];
            #pragma unroll
            for (int i = 0; i < 4; i++)
                q4[i] = *(const float4*)&Qs[(ty * 4 + i) * 64 + d4];
            #pragma unroll
            for (int j = 0; j < 4; j++) {
                int n  = tx * 4 + j;
                int sw = d4 ^ (((n >> 2) & 7) << 3);
                k4[j] = *(const float4*)&Ks[n * 64 + sw];
            }
            #pragma unroll
            for (int i = 0; i < 4; i++)
                #pragma unroll
                for (int j = 0; j < 4; j++)
                    s[i][j] += q4[i].x * k4[j].x + q4[i].y * k4[j].y
                             + q4[i].z * k4[j].z + q4[i].w * k4[j].w;
        }

        // Causal mask on the diagonal tile
        if (kt == qt) {
            #pragma unroll
            for (int i = 0; i < 4; i++)
                #pragma unroll
                for (int j = 0; j < 4; j++)
                    if (tx * 4 + j > ty * 4 + i) s[i][j] = -1e30f;
        }

        // Online softmax per row (reduce over the 16 tx lanes in the half-warp)
        #pragma unroll
        for (int i = 0; i < 4; i++) {
            float tm = fmaxf(fmaxf(s[i][0], s[i][1]), fmaxf(s[i][2], s[i][3]));
            #pragma unroll
            for (int ofs = 1; ofs < 16; ofs <<= 1)
                tm = fmaxf(tm, __shfl_xor_sync(0xffffffffu, tm, ofs));
            float nm   = fmaxf(m_i[i], tm);
            float corr = __expf(m_i[i] - nm);
            m_i[i] = nm;
            float ts = 0.f;
            #pragma unroll
            for (int j = 0; j < 4; j++) {
                float p = __expf(s[i][j] - nm);
                s[i][j] = p;
                ts += p;
            }
            #pragma unroll
            for (int ofs = 1; ofs < 16; ofs <<= 1)
                ts += __shfl_xor_sync(0xffffffffu, ts, ofs);
            l_i[i] = l_i[i] * corr + ts;
            #pragma unroll
            for (int j = 0; j < 4; j++) o[i][j] *= corr;
            *(float4*)&Ps[(ty * 4 + i) * 64 + tx * 4] =
                make_float4(s[i][0], s[i][1], s[i][2], s[i][3]);
        }
        __syncthreads();

        // O += P V  (thread owns rows 4ty.., d-cols 4tx..)
        #pragma unroll
        for (int nb = 0; nb < 64; nb += 4) {
            float4 p4[4], v4[4];
            #pragma unroll
            for (int i = 0; i < 4; i++)
                p4[i] = *(const float4*)&Ps[(ty * 4 + i) * 64 + nb];
            #pragma unroll
            for (int nn = 0; nn < 4; nn++)
                v4[nn] = *(const float4*)&Vs[(nb + nn) * 64 + tx * 4];
            #pragma unroll
            for (int i = 0; i < 4; i++) {
                o[i][0] += p4[i].x * v4[0].x + p4[i].y * v4[1].x
                         + p4[i].z * v4[2].x + p4[i].w * v4[3].x;
                o[i][1] += p4[i].x * v4[0].y + p4[i].y * v4[1].y
                         + p4[i].z * v4[2].y + p4[i].w * v4[3].y;
                o[i][2] += p4[i].x * v4[0].z + p4[i].y * v4[1].z
                         + p4[i].z * v4[2].z + p4[i].w * v4[3].z;
                o[i][3] += p4[i].x * v4[0].w + p4[i].y * v4[1].w
                         + p4[i].z * v4[2].w + p4[i].w * v4[3].w;
            }
        }
        __syncthreads();
    }

    // Normalize and write to y in [B,T,C] layout (C index = h*64 + d)
    #pragma unroll
    for (int i = 0; i < 4; i++) {
        float inv = 1.0f / l_i[i];
        int t = qt * 64 + ty * 4 + i;
        float4 ov = make_float4(o[i][0] * inv, o[i][1] * inv,
                                o[i][2] * inv, o[i][3] * inv);
        *(float4*)&g_y[((size_t)(b * T_SEQ + t)) * C_DIM + h * HD + tx * 4] = ov;
    }
}

// ---------------------------------------------------------------------------
// Output projection: g_y[4096,1024] @ W_out[1024,1024] + b_out -> d_out
// ---------------------------------------------------------------------------
__global__ __launch_bounds__(256) void out_gemm_kernel(
    const float* __restrict__ W, const float* __restrict__ bias,
    float* __restrict__ out)
{
    const int K = C_DIM, N = C_DIM;
    __shared__ float As[8][128];
    __shared__ float Bs[8][128];

    int tid = threadIdx.x;
    int ty  = tid >> 4, tx = tid & 15;
    int row0 = blockIdx.y * 128, col0 = blockIdx.x * 128;

    int a_row = tid >> 1;
    int a_col = (tid & 1) << 2;
    int b_row = tid >> 5;
    int b_col = (tid & 31) << 2;

    const float* Aptr = g_y + (size_t)(row0 + a_row) * K + a_col;
    const float* Bptr = W + (size_t)b_row * N + col0 + b_col;

    float acc[8][8];
    #pragma unroll
    for (int i = 0; i < 8; i++)
        #pragma unroll
        for (int j = 0; j < 8; j++) acc[i][j] = 0.f;

    for (int k0 = 0; k0 < K; k0 += 8) {
        float4 av = *(const float4*)(Aptr + k0);
        float4 bv = *(const float4*)(Bptr + (size_t)k0 * N);
        As[a_col + 0][a_row] = av.x;
        As[a_col + 1][a_row] = av.y;
        As[a_col + 2][a_row] = av.z;
        As[a_col + 3][a_row] = av.w;
        *(float4*)&Bs[b_row][b_col] = bv;
        __syncthreads();

        #pragma unroll
        for (int kk = 0; kk < 8; kk++) {
            float4 a0 = *(const float4*)&As[kk][ty * 8];
            float4 a1 = *(const float4*)&As[kk][ty * 8 + 4];
            float4 b0 = *(const float4*)&Bs[kk][tx * 8];
            float4 b1 = *(const float4*)&Bs[kk][tx * 8 + 4];
            float ar[8] = {a0.x, a0.y, a0.z, a0.w, a1.x, a1.y, a1.z, a1.w};
            float br[8] = {b0.x, b0.y, b0.z, b0.w, b1.x, b1.y, b1.z, b1.w};
            #pragma unroll
            for (int i = 0; i < 8; i++)
                #pragma unroll
                for (int j = 0; j < 8; j++)
                    acc[i][j] += ar[i] * br[j];
        }
        __syncthreads();
    }

    #pragma unroll
    for (int i = 0; i < 8; i++) {
        int r = row0 + ty * 8 + i;
        #pragma unroll
        for (int j = 0; j < 8; j++) {
            int jc = col0 + tx * 8 + j;
            out[(size_t)r * N + jc] = acc[i][j] + bias[jc];
        }
    }
}

// ---------------------------------------------------------------------------
extern "C" void kernel_launch(void* const* d_in, const int* in_sizes, int n_in,
                              void* d_out, int out_size)
{
    (void)in_sizes; (void)n_in; (void)out_size;
    const float* x      = (const float*)d_in[0];
    // d_in[1] = causal mask (tril) -- structure hardcoded in attn_kernel
    const float* W_qkv  = (const float*)d_in[2];
    const float* b_qkv  = (const float*)d_in[3];
    const float* W_out  = (const float*)d_in[4];
    const float* b_out  = (const float*)d_in[5];
    float* out = (float*)d_out;

    qkv_gemm_kernel<<<dim3(N_QKV / 128, M_ROWS / 128), 256>>>(x, W_qkv, b_qkv);

    cudaFuncSetAttribute(attn_kernel,
                         cudaFuncAttributeMaxDynamicSharedMemorySize, 65536);
    attn_kernel<<<dim3(T_SEQ / 64, B_SZ * NH), 256, 65536>>>();

    out_gemm_kernel<<<dim3(C_DIM / 128, M_ROWS / 128), 256>>>(W_out, b_out, out);
}

// round 3
// speedup vs baseline: 2.1142x; 2.1142x over previous
#include <cuda_runtime.h>
#include <cuda_bf16.h>

#define B_SZ 2
#define T_SEQ 2048
#define C_DIM 1024
#define NH 16
#define HD 64
#define N_QKV 3072

typedef __nv_bfloat16 bf16;
typedef unsigned int u32;

#define QKV_ELEMS ((size_t)B_SZ*NH*T_SEQ*HD)
__device__ bf16 g_qh[QKV_ELEMS], g_ql[QKV_ELEMS];
__device__ bf16 g_kh[QKV_ELEMS], g_kl[QKV_ELEMS];
__device__ bf16 g_vh[QKV_ELEMS], g_vl[QKV_ELEMS];
__device__ bf16 g_yh[QKV_ELEMS], g_yl[QKV_ELEMS];

__device__ __forceinline__ u32 pack2(float x, float y){
    u32 a = (u32)__bfloat16_as_ushort(__float2bfloat16(x));
    u32 b = (u32)__bfloat16_as_ushort(__float2bfloat16(y));
    return a | (b<<16);
}
__device__ __forceinline__ void split2(float x, float y, u32 &hi, u32 &lo){
    bf16 hx = __float2bfloat16(x), hy = __float2bfloat16(y);
    hi = (u32)__bfloat16_as_ushort(hx) | ((u32)__bfloat16_as_ushort(hy)<<16);
    lo = pack2(x - __bfloat162float(hx), y - __bfloat162float(hy));
}
__device__ __forceinline__ void mma_bf16(float* d, const u32* a, u32 b0, u32 b1){
    asm volatile("mma.sync.aligned.m16n8k16.row.col.f32.bf16.bf16.f32 "
      "{%0,%1,%2,%3},{%4,%5,%6,%7},{%8,%9},{%0,%1,%2,%3};\n"
      : "+f"(d[0]),"+f"(d[1]),"+f"(d[2]),"+f"(d[3])
      : "r"(a[0]),"r"(a[1]),"r"(a[2]),"r"(a[3]),"r"(b0),"r"(b1));
}
__device__ __forceinline__ void ldm4(u32* r, const bf16* p){
    u32 sa = (u32)__cvta_generic_to_shared(p);
    asm volatile("ldmatrix.sync.aligned.m8n8.x4.shared.b16 {%0,%1,%2,%3},[%4];"
      : "=r"(r[0]),"=r"(r[1]),"=r"(r[2]),"=r"(r[3]) : "r"(sa));
}
__device__ __forceinline__ u32 prmt(u32 a, u32 b, u32 sel){
    u32 r; asm("prmt.b32 %0,%1,%2,%3;" : "=r"(r) : "r"(a),"r"(b),"r"(sel));
    return r;
}

// ---------------------------------------------------------------------------
// GEMM: 128x128 tile, KB=32, bf16x3 split mma. MODE0: x@Wqkv+b -> split qkv.
// MODE1: y(bf16 hi/lo)@Wout+b -> fp32 out.
// ---------------------------------------------------------------------------
#define SA 40
#define SB 136

template<int MODE>
__global__ __launch_bounds__(256) void gemm_kernel(
    const float* __restrict__ Afp, const float* __restrict__ W,
    const float* __restrict__ bias, float* __restrict__ outp)
{
    const int N = (MODE==0) ? N_QKV : C_DIM;
    __shared__ bf16 Ah[128*SA], Al[128*SA];
    __shared__ u32  Bh[16*SB],  Bl[16*SB];

    int tid = threadIdx.x, lane = tid&31, wid = tid>>5;
    int g = lane>>2, c = lane&3;
    int row0 = blockIdx.y*128, col0 = blockIdx.x*128;
    int wm = (wid>>2)*64, wn = (wid&3)*32;

    float acc[4][4][4];
    #pragma unroll
    for (int i=0;i<4;i++)
        #pragma unroll
        for (int j=0;j<4;j++)
            #pragma unroll
            for (int q=0;q<4;q++) acc[i][j][q] = 0.f;

    for (int k0=0; k0<C_DIM; k0+=32) {
        if (MODE==0) {
            #pragma unroll
            for (int i=0;i<4;i++){
                int e = i*256+tid; int r = e>>3, kq = (e&7)*4;
                float4 v = *(const float4*)(Afp + (size_t)(row0+r)*C_DIM + k0+kq);
                u32 h0,l0,h1,l1; split2(v.x,v.y,h0,l0); split2(v.z,v.w,h1,l1);
                *(u32*)(Ah + r*SA + kq)   = h0; *(u32*)(Ah + r*SA + kq+2) = h1;
                *(u32*)(Al + r*SA + kq)   = l0; *(u32*)(Al + r*SA + kq+2) = l1;
            }
        } else {
            #pragma unroll
            for (int i=0;i<2;i++){
                int e = i*256+tid; int r = e>>2, kq = (e&3)*8;
                size_t off = (size_t)(row0+r)*C_DIM + k0+kq;
                *(uint4*)(Ah + r*SA + kq) = *(const uint4*)(g_yh + off);
                *(uint4*)(Al + r*SA + kq) = *(const uint4*)(g_yl + off);
            }
        }
        #pragma unroll
        for (int i=0;i<2;i++){
            int w = i*256+tid; int kp = w>>5, n0 = (w&31)*4;
            const float* p0 = W + (size_t)(k0+2*kp)*N + col0+n0;
            float4 r0 = *(const float4*)p0;
            float4 r1 = *(const float4*)(p0+N);
            u32 bh[4], bl[4];
            split2(r0.x, r1.x, bh[0], bl[0]);
            split2(r0.y, r1.y, bh[1], bl[1]);
            split2(r0.z, r1.z, bh[2], bl[2]);
            split2(r0.w, r1.w, bh[3], bl[3]);
            *(uint4*)(Bh + kp*SB + n0) = make_uint4(bh[0],bh[1],bh[2],bh[3]);
            *(uint4*)(Bl + kp*SB + n0) = make_uint4(bl[0],bl[1],bl[2],bl[3]);
        }
        __syncthreads();

        #pragma unroll
        for (int kc=0;kc<2;kc++){
            u32 ah[4][4], al[4][4];
            #pragma unroll
            for (int mt=0;mt<4;mt++){
                int r = wm + mt*16 + (lane&7) + ((lane>>3)&1)*8;
                int cc = kc*16 + (lane>>4)*8;
                ldm4(ah[mt], Ah + r*SA + cc);
                ldm4(al[mt], Al + r*SA + cc);
            }
            #pragma unroll
            for (int nt=0;nt<4;nt++){
                int bi = (8*kc+c)*SB + wn + nt*8 + g;
                u32 bh0 = Bh[bi], bh1 = Bh[bi+4*SB];
                u32 bl0 = Bl[bi], bl1 = Bl[bi+4*SB];
                #pragma unroll
                for (int mt=0;mt<4;mt++){
                    mma_bf16(acc[mt][nt], ah[mt], bh0, bh1);
                    mma_bf16(acc[mt][nt], ah[mt], bl0, bl1);
                    mma_bf16(acc[mt][nt], al[mt], bh0, bh1);
                }
            }
        }
        __syncthreads();
    }

    #pragma unroll
    for (int mt=0;mt<4;mt++){
        int rg = row0 + wm + mt*16 + g;
        #pragma unroll
        for (int nt=0;nt<4;nt++){
            int jc = col0 + wn + nt*8 + 2*c;
            float bv0 = bias[jc], bv1 = bias[jc+1];
            float v00 = acc[mt][nt][0]+bv0, v01 = acc[mt][nt][1]+bv1;
            float v10 = acc[mt][nt][2]+bv0, v11 = acc[mt][nt][3]+bv1;
            if (MODE==0) {
                int part = jc>>10, cc2 = jc&1023, h = cc2>>6, d = cc2&63;
                if (part==0){ v00*=0.125f; v01*=0.125f; v10*=0.125f; v11*=0.125f; }
                bf16 *ph = (part==0)?g_qh:(part==1)?g_kh:g_vh;
                bf16 *pl = (part==0)?g_ql:(part==1)?g_kl:g_vl;
                int rr[2] = {rg, rg+8};
                float va[2][2] = {{v00,v01},{v10,v11}};
                #pragma unroll
                for (int ii=0;ii<2;ii++){
                    int t = rr[ii]&2047, bb = rr[ii]>>11;
                    size_t idx = (((size_t)(bb*NH+h))*T_SEQ + t)*HD + d;
                    u32 hi, lo; split2(va[ii][0], va[ii][1], hi, lo);
                    *(u32*)(ph+idx) = hi; *(u32*)(pl+idx) = lo;
                }
            } else {
                *(float2*)(outp + (size_t)rg*C_DIM + jc)     = make_float2(v00,v01);
                *(float2*)(outp + (size_t)(rg+8)*C_DIM + jc) = make_float2(v10,v11);
            }
        }
    }
}

// ---------------------------------------------------------------------------
// Flash attention, bf16x3 mma. Block = 128 Q rows x (b,h). 8 warps, 16 rows ea.
// ---------------------------------------------------------------------------
#define SK 36

__global__ __launch_bounds__(256) void attn_kernel()
{
    __shared__ u32 Kph[64*SK], Kpl[64*SK], Vph[64*SK], Vpl[64*SK];

    int tid = threadIdx.x, lane = tid&31, wid = tid>>5;
    int g = lane>>2, c = lane&3;
    int qt = blockIdx.x, bh = blockIdx.y;
    int b = bh>>4, h = bh&15;
    size_t base = (size_t)bh * T_SEQ * HD;
    int Q0 = qt*128, wrow = wid*16;

    // Q fragments (hoisted, already scaled)
    u32 qh[4][4], ql[4][4];
    #pragma unroll
    for (int kc=0;kc<4;kc++){
        size_t i00 = base + (size_t)(Q0+wrow+g)*HD + kc*16 + 2*c;
        size_t i10 = i00 + 8ull*HD;
        qh[kc][0] = *(const u32*)(g_qh+i00); qh[kc][1] = *(const u32*)(g_qh+i10);
        qh[kc][2] = *(const u32*)(g_qh+i00+8); qh[kc][3] = *(const u32*)(g_qh+i10+8);
        ql[kc][0] = *(const u32*)(g_ql+i00); ql[kc][1] = *(const u32*)(g_ql+i10);
        ql[kc][2] = *(const u32*)(g_ql+i00+8); ql[kc][3] = *(const u32*)(g_ql+i10+8);
    }

    float m0=-1e30f, m1=-1e30f, l0=0.f, l1=0.f;
    float o[8][4];
    #pragma unroll
    for (int i=0;i<8;i++){ o[i][0]=0.f; o[i][1]=0.f; o[i][2]=0.f; o[i][3]=0.f; }

    for (int kt=0; kt<=2*qt+1; kt++){
        int K0 = kt*64;
        {   // K pack: Kp[key][dpair] (d-pairs already adjacent in memory)
            int key = tid>>2, q4 = tid&3;
            size_t go = base + (size_t)(K0+key)*HD + q4*16;
            *(uint4*)(Kph + key*SK + q4*8)     = *(const uint4*)(g_kh+go);
            *(uint4*)(Kph + key*SK + q4*8 + 4) = *(const uint4*)(g_kh+go+8);
            *(uint4*)(Kpl + key*SK + q4*8)     = *(const uint4*)(g_kl+go);
            *(uint4*)(Kpl + key*SK + q4*8 + 4) = *(const uint4*)(g_kl+go+8);
        }
        {   // V pack: Vp[d][keypair] via prmt
            int kp = tid>>3, dd = (tid&7)*8;
            size_t r0o = base + (size_t)(K0+2*kp)*HD + dd;
            const u32* ah = (const u32*)(g_vh + r0o);
            const u32* bh2 = (const u32*)(g_vh + r0o + HD);
            const u32* al = (const u32*)(g_vl + r0o);
            const u32* bl2 = (const u32*)(g_vl + r0o + HD);
            #pragma unroll
            for (int j=0;j<4;j++){
                u32 x = ah[j], y = bh2[j];
                Vph[(dd+2*j)*SK + kp]   = prmt(x,y,0x5410);
                Vph[(dd+2*j+1)*SK + kp] = prmt(x,y,0x7632);
                x = al[j]; y = bl2[j];
                Vpl[(dd+2*j)*SK + kp]   = prmt(x,y,0x5410);
                Vpl[(dd+2*j+1)*SK + kp] = prmt(x,y,0x7632);
            }
        }
        __syncthreads();

        float s[8][4];
        #pragma unroll
        for (int i=0;i<8;i++){ s[i][0]=0.f; s[i][1]=0.f; s[i][2]=0.f; s[i][3]=0.f; }
        #pragma unroll
        for (int kc=0;kc<4;kc++){
            #pragma unroll
            for (int nt=0;nt<8;nt++){
                int bi = (nt*8+g)*SK + kc*8 + c;
                u32 bh0 = Kph[bi], bh1 = Kph[bi+4];
                u32 bl0 = Kpl[bi], bl1 = Kpl[bi+4];
                mma_bf16(s[nt], qh[kc], bh0, bh1);
                mma_bf16(s[nt], qh[kc], bl0, bl1);
                mma_bf16(s[nt], ql[kc], bh0, bh1);
            }
        }

        if (kt >= 2*qt){
            int r0 = Q0+wrow+g, r1 = r0+8;
            #pragma unroll
            for (int nt=0;nt<8;nt++){
                int kk = K0 + nt*8 + 2*c;
                if (kk   > r0) s[nt][0] = -1e30f;
                if (kk+1 > r0) s[nt][1] = -1e30f;
                if (kk   > r1) s[nt][2] = -1e30f;
                if (kk+1 > r1) s[nt][3] = -1e30f;
            }
        }

        float tm0=-1e30f, tm1=-1e30f;
        #pragma unroll
        for (int nt=0;nt<8;nt++){
            tm0 = fmaxf(tm0, fmaxf(s[nt][0], s[nt][1]));
            tm1 = fmaxf(tm1, fmaxf(s[nt][2], s[nt][3]));
        }
        tm0 = fmaxf(tm0, __shfl_xor_sync(0xffffffffu, tm0, 1));
        tm0 = fmaxf(tm0, __shfl_xor_sync(0xffffffffu, tm0, 2));
        tm1 = fmaxf(tm1, __shfl_xor_sync(0xffffffffu, tm1, 1));
        tm1 = fmaxf(tm1, __shfl_xor_sync(0xffffffffu, tm1, 2));
        float nm0 = fmaxf(m0, tm0), nm1 = fmaxf(m1, tm1);
        float cor0 = __expf(m0-nm0), cor1 = __expf(m1-nm1);
        m0 = nm0; m1 = nm1;
        float ts0 = 0.f, ts1 = 0.f;
        #pragma unroll
        for (int nt=0;nt<8;nt++){
            s[nt][0] = __expf(s[nt][0]-nm0); ts0 += s[nt][0];
            s[nt][1] = __expf(s[nt][1]-nm0); ts0 += s[nt][1];
            s[nt][2] = __expf(s[nt][2]-nm1); ts1 += s[nt][2];
            s[nt][3] = __expf(s[nt][3]-nm1); ts1 += s[nt][3];
        }
        ts0 += __shfl_xor_sync(0xffffffffu, ts0, 1);
        ts0 += __shfl_xor_sync(0xffffffffu, ts0, 2);
        ts1 += __shfl_xor_sync(0xffffffffu, ts1, 1);
        ts1 += __shfl_xor_sync(0xffffffffu, ts1, 2);
        l0 = l0*cor0 + ts0; l1 = l1*cor1 + ts1;
        #pragma unroll
        for (int dt=0;dt<8;dt++){
            o[dt][0]*=cor0; o[dt][1]*=cor0; o[dt][2]*=cor1; o[dt][3]*=cor1;
        }

        #pragma unroll
        for (int kc=0;kc<4;kc++){
            u32 ph_[4], pl_[4];
            split2(s[2*kc][0],   s[2*kc][1],   ph_[0], pl_[0]);
            split2(s[2*kc][2],   s[2*kc][3],   ph_[1], pl_[1]);
            split2(s[2*kc+1][0], s[2*kc+1][1], ph_[2], pl_[2]);
            split2(s[2*kc+1][2], s[2*kc+1][3], ph_[3], pl_[3]);
            #pragma unroll
            for (int dt=0;dt<8;dt++){
                int bi = (dt*8+g)*SK + kc*8 + c;
                u32 vh0 = Vph[bi], vh1 = Vph[bi+4];
                u32 vl0 = Vpl[bi], vl1 = Vpl[bi+4];
                mma_bf16(o[dt], ph_, vh0, vh1);
                mma_bf16(o[dt], ph_, vl0, vl1);
                mma_bf16(o[dt], pl_, vh0, vh1);
            }
        }
        __syncthreads();
    }

    float i0 = 1.f/l0, i1 = 1.f/l1;
    size_t yb0 = ((size_t)(b*T_SEQ) + Q0+wrow+g)*C_DIM + h*HD;
    size_t yb1 = yb0 + 8ull*C_DIM;
    #pragma unroll
    for (int dt=0;dt<8;dt++){
        int dc = dt*8 + 2*c;
        u32 hi, lo;
        split2(o[dt][0]*i0, o[dt][1]*i0, hi, lo);
        *(u32*)(g_yh+yb0+dc) = hi; *(u32*)(g_yl+yb0+dc) = lo;
        split2(o[dt][2]*i1, o[dt][3]*i1, hi, lo);
        *(u32*)(g_yh+yb1+dc) = hi; *(u32*)(g_yl+yb1+dc) = lo;
    }
}

// ---------------------------------------------------------------------------
extern "C" void kernel_launch(void* const* d_in, const int* in_sizes, int n_in,
                              void* d_out, int out_size)
{
    (void)in_sizes; (void)n_in; (void)out_size;
    const float* x     = (const float*)d_in[0];
    const float* W_qkv = (const float*)d_in[2];
    const float* b_qkv = (const float*)d_in[3];
    const float* W_out = (const float*)d_in[4];
    const float* b_out = (const float*)d_in[5];
    float* out = (float*)d_out;

    gemm_kernel<0><<<dim3(N_QKV/128, 4096/128), 256>>>(x, W_qkv, b_qkv, nullptr);
    attn_kernel<<<dim3(T_SEQ/128, B_SZ*NH), 256>>>();
    gemm_kernel<1><<<dim3(C_DIM/128, 4096/128), 256>>>(nullptr, W_out, b_out, out);
}

// round 6
// speedup vs baseline: 2.2033x; 1.0421x over previous
#include <cuda_runtime.h>
#include <cuda_bf16.h>

#define B_SZ 2
#define T_SEQ 2048
#define C_DIM 1024
#define NH 16
#define HD 64
#define N_QKV 3072

typedef __nv_bfloat16 bf16;
typedef unsigned int u32;

#define QKV_ELEMS ((size_t)B_SZ*NH*T_SEQ*HD)
__device__ bf16 g_qh[QKV_ELEMS], g_ql[QKV_ELEMS];
__device__ bf16 g_kh[QKV_ELEMS], g_kl[QKV_ELEMS];
__device__ bf16 g_vh[QKV_ELEMS], g_vl[QKV_ELEMS];
__device__ bf16 g_yh[QKV_ELEMS], g_yl[QKV_ELEMS];

__device__ __forceinline__ u32 pack2(float x, float y){
    u32 a = (u32)__bfloat16_as_ushort(__float2bfloat16(x));
    u32 b = (u32)__bfloat16_as_ushort(__float2bfloat16(y));
    return a | (b<<16);
}
__device__ __forceinline__ void split2(float x, float y, u32 &hi, u32 &lo){
    bf16 hx = __float2bfloat16(x), hy = __float2bfloat16(y);
    hi = (u32)__bfloat16_as_ushort(hx) | ((u32)__bfloat16_as_ushort(hy)<<16);
    lo = pack2(x - __bfloat162float(hx), y - __bfloat162float(hy));
}
__device__ __forceinline__ void mma_bf16(float* d, const u32* a, u32 b0, u32 b1){
    asm volatile("mma.sync.aligned.m16n8k16.row.col.f32.bf16.bf16.f32 "
      "{%0,%1,%2,%3},{%4,%5,%6,%7},{%8,%9},{%0,%1,%2,%3};\n"
      : "+f"(d[0]),"+f"(d[1]),"+f"(d[2]),"+f"(d[3])
      : "r"(a[0]),"r"(a[1]),"r"(a[2]),"r"(a[3]),"r"(b0),"r"(b1));
}
__device__ __forceinline__ void ldm4(u32* r, const bf16* p){
    u32 sa = (u32)__cvta_generic_to_shared(p);
    asm volatile("ldmatrix.sync.aligned.m8n8.x4.shared.b16 {%0,%1,%2,%3},[%4];"
      : "=r"(r[0]),"=r"(r[1]),"=r"(r[2]),"=r"(r[3]) : "r"(sa));
}
__device__ __forceinline__ u32 prmt(u32 a, u32 b, u32 sel){
    u32 r; asm("prmt.b32 %0,%1,%2,%3;" : "=r"(r) : "r"(a),"r"(b),"r"(sel));
    return r;
}

// ---------------------------------------------------------------------------
// GEMM: 128x128 tile, KB=32, bf16x3 split mma, register-staged prefetch.
// MODE0: x@Wqkv+b -> split qkv.  MODE1: y(bf16 hi/lo)@Wout+b -> fp32 out.
// ---------------------------------------------------------------------------
#define SA 40
#define SB 136

template<int MODE>
__global__ __launch_bounds__(256) void gemm_kernel(
    const float* __restrict__ Afp, const float* __restrict__ W,
    const float* __restrict__ bias, float* __restrict__ outp)
{
    const int N = (MODE==0) ? N_QKV : C_DIM;
    __shared__ bf16 Ah[128*SA], Al[128*SA];
    __shared__ u32  Bh[16*SB],  Bl[16*SB];

    int tid = threadIdx.x, lane = tid&31, wid = tid>>5;
    int g = lane>>2, c = lane&3;
    int row0 = blockIdx.y*128, col0 = blockIdx.x*128;
    int wm = (wid>>2)*64, wn = (wid&3)*32;

    float acc[4][4][4];
    #pragma unroll
    for (int i=0;i<4;i++)
        #pragma unroll
        for (int j=0;j<4;j++)
            #pragma unroll
            for (int q=0;q<4;q++) acc[i][j][q] = 0.f;

    // register staging
    float4 ra[4];
    uint4  rah[2], ral[2];
    float4 rb0[2], rb1[2];

    auto ldg = [&](int k0){
        if (MODE==0) {
            #pragma unroll
            for (int i=0;i<4;i++){
                int e = i*256+tid; int r = e>>3, kq = (e&7)*4;
                ra[i] = *(const float4*)(Afp + (size_t)(row0+r)*C_DIM + k0+kq);
            }
        } else {
            #pragma unroll
            for (int i=0;i<2;i++){
                int e = i*256+tid; int r = e>>2, kq = (e&3)*8;
                size_t off = (size_t)(row0+r)*C_DIM + k0+kq;
                rah[i] = *(const uint4*)(g_yh + off);
                ral[i] = *(const uint4*)(g_yl + off);
            }
        }
        #pragma unroll
        for (int i=0;i<2;i++){
            int w = i*256+tid; int kp = w>>5, n0 = (w&31)*4;
            const float* p0 = W + (size_t)(k0+2*kp)*N + col0+n0;
            rb0[i] = *(const float4*)p0;
            rb1[i] = *(const float4*)(p0+N);
        }
    };
    auto sts = [&](){
        if (MODE==0) {
            #pragma unroll
            for (int i=0;i<4;i++){
                int e = i*256+tid; int r = e>>3, kq = (e&7)*4;
                u32 h0,l0,h1,l1; split2(ra[i].x,ra[i].y,h0,l0); split2(ra[i].z,ra[i].w,h1,l1);
                *(u32*)(Ah + r*SA + kq)   = h0; *(u32*)(Ah + r*SA + kq+2) = h1;
                *(u32*)(Al + r*SA + kq)   = l0; *(u32*)(Al + r*SA + kq+2) = l1;
            }
        } else {
            #pragma unroll
            for (int i=0;i<2;i++){
                int e = i*256+tid; int r = e>>2, kq = (e&3)*8;
                *(uint4*)(Ah + r*SA + kq) = rah[i];
                *(uint4*)(Al + r*SA + kq) = ral[i];
            }
        }
        #pragma unroll
        for (int i=0;i<2;i++){
            int w = i*256+tid; int kp = w>>5, n0 = (w&31)*4;
            u32 h[4], l[4];
            split2(rb0[i].x, rb1[i].x, h[0], l[0]);
            split2(rb0[i].y, rb1[i].y, h[1], l[1]);
            split2(rb0[i].z, rb1[i].z, h[2], l[2]);
            split2(rb0[i].w, rb1[i].w, h[3], l[3]);
            *(uint4*)(Bh + kp*SB + n0) = make_uint4(h[0],h[1],h[2],h[3]);
            *(uint4*)(Bl + kp*SB + n0) = make_uint4(l[0],l[1],l[2],l[3]);
        }
    };

    ldg(0); sts(); __syncthreads();

    for (int k0=0; k0<C_DIM; k0+=32) {
        if (k0+32 < C_DIM) ldg(k0+32);   // prefetch next tile into registers

        #pragma unroll
        for (int kc=0;kc<2;kc++){
            u32 ah[4][4], al[4][4];
            #pragma unroll
            for (int mt=0;mt<4;mt++){
                int r = wm + mt*16 + (lane&7) + ((lane>>3)&1)*8;
                int cc = kc*16 + (lane>>4)*8;
                ldm4(ah[mt], Ah + r*SA + cc);
                ldm4(al[mt], Al + r*SA + cc);
            }
            #pragma unroll
            for (int nt=0;nt<4;nt++){
                int bi = (8*kc+c)*SB + wn + nt*8 + g;
                u32 bh0 = Bh[bi], bh1 = Bh[bi+4*SB];
                u32 bl0 = Bl[bi], bl1 = Bl[bi+4*SB];
                #pragma unroll
                for (int mt=0;mt<4;mt++){
                    mma_bf16(acc[mt][nt], ah[mt], bh0, bh1);
                    mma_bf16(acc[mt][nt], ah[mt], bl0, bl1);
                    mma_bf16(acc[mt][nt], al[mt], bh0, bh1);
                }
            }
        }
        __syncthreads();
        if (k0+32 < C_DIM){ sts(); __syncthreads(); }
    }

    #pragma unroll
    for (int mt=0;mt<4;mt++){
        int rg = row0 + wm + mt*16 + g;
        #pragma unroll
        for (int nt=0;nt<4;nt++){
            int jc = col0 + wn + nt*8 + 2*c;
            float bv0 = bias[jc], bv1 = bias[jc+1];
            float v00 = acc[mt][nt][0]+bv0, v01 = acc[mt][nt][1]+bv1;
            float v10 = acc[mt][nt][2]+bv0, v11 = acc[mt][nt][3]+bv1;
            if (MODE==0) {
                int part = jc>>10, cc2 = jc&1023, h = cc2>>6, d = cc2&63;
                if (part==0){ v00*=0.125f; v01*=0.125f; v10*=0.125f; v11*=0.125f; }
                bf16 *ph = (part==0)?g_qh:(part==1)?g_kh:g_vh;
                bf16 *pl = (part==0)?g_ql:(part==1)?g_kl:g_vl;
                int rr[2] = {rg, rg+8};
                float va[2][2] = {{v00,v01},{v10,v11}};
                #pragma unroll
                for (int ii=0;ii<2;ii++){
                    int t = rr[ii]&2047, bb = rr[ii]>>11;
                    size_t idx = (((size_t)(bb*NH+h))*T_SEQ + t)*HD + d;
                    u32 hi, lo; split2(va[ii][0], va[ii][1], hi, lo);
                    *(u32*)(ph+idx) = hi; *(u32*)(pl+idx) = lo;
                }
            } else {
                *(float2*)(outp + (size_t)rg*C_DIM + jc)     = make_float2(v00,v01);
                *(float2*)(outp + (size_t)(rg+8)*C_DIM + jc) = make_float2(v10,v11);
            }
        }
    }
}

// ---------------------------------------------------------------------------
// Flash attention, bf16x3 mma (identical to the passing round-3 version).
// ---------------------------------------------------------------------------
#define SK 36

__global__ __launch_bounds__(256) void attn_kernel()
{
    __shared__ u32 Kph[64*SK], Kpl[64*SK], Vph[64*SK], Vpl[64*SK];

    int tid = threadIdx.x, lane = tid&31, wid = tid>>5;
    int g = lane>>2, c = lane&3;
    int qt = blockIdx.x, bh = blockIdx.y;
    int b = bh>>4, h = bh&15;
    size_t base = (size_t)bh * T_SEQ * HD;
    int Q0 = qt*128, wrow = wid*16;

    u32 qh[4][4], ql[4][4];
    #pragma unroll
    for (int kc=0;kc<4;kc++){
        size_t i00 = base + (size_t)(Q0+wrow+g)*HD + kc*16 + 2*c;
        size_t i10 = i00 + 8ull*HD;
        qh[kc][0] = *(const u32*)(g_qh+i00); qh[kc][1] = *(const u32*)(g_qh+i10);
        qh[kc][2] = *(const u32*)(g_qh+i00+8); qh[kc][3] = *(const u32*)(g_qh+i10+8);
        ql[kc][0] = *(const u32*)(g_ql+i00); ql[kc][1] = *(const u32*)(g_ql+i10);
        ql[kc][2] = *(const u32*)(g_ql+i00+8); ql[kc][3] = *(const u32*)(g_ql+i10+8);
    }

    float m0=-1e30f, m1=-1e30f, l0=0.f, l1=0.f;
    float o[8][4];
    #pragma unroll
    for (int i=0;i<8;i++){ o[i][0]=0.f; o[i][1]=0.f; o[i][2]=0.f; o[i][3]=0.f; }

    for (int kt=0; kt<=2*qt+1; kt++){
        int K0 = kt*64;
        {
            int key = tid>>2, q4 = tid&3;
            size_t go = base + (size_t)(K0+key)*HD + q4*16;
            *(uint4*)(Kph + key*SK + q4*8)     = *(const uint4*)(g_kh+go);
            *(uint4*)(Kph + key*SK + q4*8 + 4) = *(const uint4*)(g_kh+go+8);
            *(uint4*)(Kpl + key*SK + q4*8)     = *(const uint4*)(g_kl+go);
            *(uint4*)(Kpl + key*SK + q4*8 + 4) = *(const uint4*)(g_kl+go+8);
        }
        {
            int kp = tid>>3, dd = (tid&7)*8;
            size_t r0o = base + (size_t)(K0+2*kp)*HD + dd;
            const u32* ah = (const u32*)(g_vh + r0o);
            const u32* bh2 = (const u32*)(g_vh + r0o + HD);
            const u32* al = (const u32*)(g_vl + r0o);
            const u32* bl2 = (const u32*)(g_vl + r0o + HD);
            #pragma unroll
            for (int j=0;j<4;j++){
                u32 x = ah[j], y = bh2[j];
                Vph[(dd+2*j)*SK + kp]   = prmt(x,y,0x5410);
                Vph[(dd+2*j+1)*SK + kp] = prmt(x,y,0x7632);
                x = al[j]; y = bl2[j];
                Vpl[(dd+2*j)*SK + kp]   = prmt(x,y,0x5410);
                Vpl[(dd+2*j+1)*SK + kp] = prmt(x,y,0x7632);
            }
        }
        __syncthreads();

        float s[8][4];
        #pragma unroll
        for (int i=0;i<8;i++){ s[i][0]=0.f; s[i][1]=0.f; s[i][2]=0.f; s[i][3]=0.f; }
        #pragma unroll
        for (int kc=0;kc<4;kc++){
            #pragma unroll
            for (int nt=0;nt<8;nt++){
                int bi = (nt*8+g)*SK + kc*8 + c;
                u32 bh0 = Kph[bi], bh1 = Kph[bi+4];
                u32 bl0 = Kpl[bi], bl1 = Kpl[bi+4];
                mma_bf16(s[nt], qh[kc], bh0, bh1);
                mma_bf16(s[nt], qh[kc], bl0, bl1);
                mma_bf16(s[nt], ql[kc], bh0, bh1);
            }
        }

        if (kt >= 2*qt){
            int r0 = Q0+wrow+g, r1 = r0+8;
            #pragma unroll
            for (int nt=0;nt<8;nt++){
                int kk = K0 + nt*8 + 2*c;
                if (kk   > r0) s[nt][0] = -1e30f;
                if (kk+1 > r0) s[nt][1] = -1e30f;
                if (kk   > r1) s[nt][2] = -1e30f;
                if (kk+1 > r1) s[nt][3] = -1e30f;
            }
        }

        float tm0=-1e30f, tm1=-1e30f;
        #pragma unroll
        for (int nt=0;nt<8;nt++){
            tm0 = fmaxf(tm0, fmaxf(s[nt][0], s[nt][1]));
            tm1 = fmaxf(tm1, fmaxf(s[nt][2], s[nt][3]));
        }
        tm0 = fmaxf(tm0, __shfl_xor_sync(0xffffffffu, tm0, 1));
        tm0 = fmaxf(tm0, __shfl_xor_sync(0xffffffffu, tm0, 2));
        tm1 = fmaxf(tm1, __shfl_xor_sync(0xffffffffu, tm1, 1));
        tm1 = fmaxf(tm1, __shfl_xor_sync(0xffffffffu, tm1, 2));
        float nm0 = fmaxf(m0, tm0), nm1 = fmaxf(m1, tm1);
        float cor0 = __expf(m0-nm0), cor1 = __expf(m1-nm1);
        m0 = nm0; m1 = nm1;
        float ts0 = 0.f, ts1 = 0.f;
        #pragma unroll
        for (int nt=0;nt<8;nt++){
            s[nt][0] = __expf(s[nt][0]-nm0); ts0 += s[nt][0];
            s[nt][1] = __expf(s[nt][1]-nm0); ts0 += s[nt][1];
            s[nt][2] = __expf(s[nt][2]-nm1); ts1 += s[nt][2];
            s[nt][3] = __expf(s[nt][3]-nm1); ts1 += s[nt][3];
        }
        ts0 += __shfl_xor_sync(0xffffffffu, ts0, 1);
        ts0 += __shfl_xor_sync(0xffffffffu, ts0, 2);
        ts1 += __shfl_xor_sync(0xffffffffu, ts1, 1);
        ts1 += __shfl_xor_sync(0xffffffffu, ts1, 2);
        l0 = l0*cor0 + ts0; l1 = l1*cor1 + ts1;
        #pragma unroll
        for (int dt=0;dt<8;dt++){
            o[dt][0]*=cor0; o[dt][1]*=cor0; o[dt][2]*=cor1; o[dt][3]*=cor1;
        }

        #pragma unroll
        for (int kc=0;kc<4;kc++){
            u32 ph_[4], pl_[4];
            split2(s[2*kc][0],   s[2*kc][1],   ph_[0], pl_[0]);
            split2(s[2*kc][2],   s[2*kc][3],   ph_[1], pl_[1]);
            split2(s[2*kc+1][0], s[2*kc+1][1], ph_[2], pl_[2]);
            split2(s[2*kc+1][2], s[2*kc+1][3], ph_[3], pl_[3]);
            #pragma unroll
            for (int dt=0;dt<8;dt++){
                int bi = (dt*8+g)*SK + kc*8 + c;
                u32 vh0 = Vph[bi], vh1 = Vph[bi+4];
                u32 vl0 = Vpl[bi], vl1 = Vpl[bi+4];
                mma_bf16(o[dt], ph_, vh0, vh1);
                mma_bf16(o[dt], ph_, vl0, vl1);
                mma_bf16(o[dt], pl_, vh0, vh1);
            }
        }
        __syncthreads();
    }

    float i0 = 1.f/l0, i1 = 1.f/l1;
    size_t yb0 = ((size_t)(b*T_SEQ) + Q0+wrow+g)*C_DIM + h*HD;
    size_t yb1 = yb0 + 8ull*C_DIM;
    #pragma unroll
    for (int dt=0;dt<8;dt++){
        int dc = dt*8 + 2*c;
        u32 hi, lo;
        split2(o[dt][0]*i0, o[dt][1]*i0, hi, lo);
        *(u32*)(g_yh+yb0+dc) = hi; *(u32*)(g_yl+yb0+dc) = lo;
        split2(o[dt][2]*i1, o[dt][3]*i1, hi, lo);
        *(u32*)(g_yh+yb1+dc) = hi; *(u32*)(g_yl+yb1+dc) = lo;
    }
}

// ---------------------------------------------------------------------------
extern "C" void kernel_launch(void* const* d_in, const int* in_sizes, int n_in,
                              void* d_out, int out_size)
{
    (void)in_sizes; (void)n_in; (void)out_size;
    const float* x     = (const float*)d_in[0];
    const float* W_qkv = (const float*)d_in[2];
    const float* b_qkv = (const float*)d_in[3];
    const float* W_out = (const float*)d_in[4];
    const float* b_out = (const float*)d_in[5];
    float* out = (float*)d_out;

    gemm_kernel<0><<<dim3(N_QKV/128, 4096/128), 256>>>(x, W_qkv, b_qkv, nullptr);
    attn_kernel<<<dim3(T_SEQ/128, B_SZ*NH), 256>>>();
    gemm_kernel<1><<<dim3(C_DIM/128, 4096/128), 256>>>(nullptr, W_out, b_out, out);
}

// round 7
// speedup vs baseline: 2.2127x; 1.0043x over previous
#include <cuda_runtime.h>
#include <cuda_bf16.h>

#define B_SZ 2
#define T_SEQ 2048
#define C_DIM 1024
#define NH 16
#define HD 64
#define N_QKV 3072

typedef __nv_bfloat16 bf16;
typedef unsigned int u32;

#define QKV_ELEMS ((size_t)B_SZ*NH*T_SEQ*HD)
__device__ bf16 g_qh[QKV_ELEMS], g_ql[QKV_ELEMS];
__device__ bf16 g_kh[QKV_ELEMS], g_kl[QKV_ELEMS];
__device__ bf16 g_vh[QKV_ELEMS], g_vl[QKV_ELEMS];
__device__ bf16 g_yh[QKV_ELEMS], g_yl[QKV_ELEMS];

__device__ __forceinline__ u32 pack2(float x, float y){
    u32 a = (u32)__bfloat16_as_ushort(__float2bfloat16(x));
    u32 b = (u32)__bfloat16_as_ushort(__float2bfloat16(y));
    return a | (b<<16);
}
__device__ __forceinline__ void split2(float x, float y, u32 &hi, u32 &lo){
    bf16 hx = __float2bfloat16(x), hy = __float2bfloat16(y);
    hi = (u32)__bfloat16_as_ushort(hx) | ((u32)__bfloat16_as_ushort(hy)<<16);
    lo = pack2(x - __bfloat162float(hx), y - __bfloat162float(hy));
}
__device__ __forceinline__ void mma_bf16(float* d, const u32* a, u32 b0, u32 b1){
    asm volatile("mma.sync.aligned.m16n8k16.row.col.f32.bf16.bf16.f32 "
      "{%0,%1,%2,%3},{%4,%5,%6,%7},{%8,%9},{%0,%1,%2,%3};\n"
      : "+f"(d[0]),"+f"(d[1]),"+f"(d[2]),"+f"(d[3])
      : "r"(a[0]),"r"(a[1]),"r"(a[2]),"r"(a[3]),"r"(b0),"r"(b1));
}
__device__ __forceinline__ void ldm4(u32* r, const bf16* p){
    u32 sa = (u32)__cvta_generic_to_shared(p);
    asm volatile("ldmatrix.sync.aligned.m8n8.x4.shared.b16 {%0,%1,%2,%3},[%4];"
      : "=r"(r[0]),"=r"(r[1]),"=r"(r[2]),"=r"(r[3]) : "r"(sa));
}
__device__ __forceinline__ u32 prmt(u32 a, u32 b, u32 sel){
    u32 r; asm("prmt.b32 %0,%1,%2,%3;" : "=r"(r) : "r"(a),"r"(b),"r"(sel));
    return r;
}

// ---------------------------------------------------------------------------
// GEMM: 128x128 tile, KB=32, bf16x3 split mma, 16 warps (32x32 warp tile),
// register-staged prefetch. MODE0: x@Wqkv+b -> split qkv.
// MODE1: y(bf16 hi/lo)@Wout+b -> fp32 out.
// ---------------------------------------------------------------------------
#define SA 40
#define SB 136

template<int MODE>
__global__ __launch_bounds__(512) void gemm_kernel(
    const float* __restrict__ Afp, const float* __restrict__ W,
    const float* __restrict__ bias, float* __restrict__ outp)
{
    const int N = (MODE==0) ? N_QKV : C_DIM;
    __shared__ bf16 Ah[128*SA], Al[128*SA];
    __shared__ u32  Bh[16*SB],  Bl[16*SB];

    int tid = threadIdx.x, lane = tid&31, wid = tid>>5;
    int g = lane>>2, c = lane&3;
    int row0 = blockIdx.y*128, col0 = blockIdx.x*128;
    int wm = (wid>>2)*32, wn = (wid&3)*32;

    float acc[2][4][4];
    #pragma unroll
    for (int i=0;i<2;i++)
        #pragma unroll
        for (int j=0;j<4;j++)
            #pragma unroll
            for (int q=0;q<4;q++) acc[i][j][q] = 0.f;

    // register staging (one k-tile ahead)
    float4 ra[2];
    uint4  rah, ral;
    float4 rb0, rb1;

    auto ldg = [&](int k0){
        if (MODE==0) {
            #pragma unroll
            for (int i=0;i<2;i++){
                int e = i*512+tid; int r = e>>3, kq = (e&7)*4;
                ra[i] = *(const float4*)(Afp + (size_t)(row0+r)*C_DIM + k0+kq);
            }
        } else {
            int r = tid>>2, kq = (tid&3)*8;
            size_t off = (size_t)(row0+r)*C_DIM + k0+kq;
            rah = *(const uint4*)(g_yh + off);
            ral = *(const uint4*)(g_yl + off);
        }
        {
            int kp = tid>>5, n0 = (tid&31)*4;
            const float* p0 = W + (size_t)(k0+2*kp)*N + col0+n0;
            rb0 = *(const float4*)p0;
            rb1 = *(const float4*)(p0+N);
        }
    };
    auto sts = [&](){
        if (MODE==0) {
            #pragma unroll
            for (int i=0;i<2;i++){
                int e = i*512+tid; int r = e>>3, kq = (e&7)*4;
                u32 h0,l0,h1,l1; split2(ra[i].x,ra[i].y,h0,l0); split2(ra[i].z,ra[i].w,h1,l1);
                *(u32*)(Ah + r*SA + kq)   = h0; *(u32*)(Ah + r*SA + kq+2) = h1;
                *(u32*)(Al + r*SA + kq)   = l0; *(u32*)(Al + r*SA + kq+2) = l1;
            }
        } else {
            int r = tid>>2, kq = (tid&3)*8;
            *(uint4*)(Ah + r*SA + kq) = rah;
            *(uint4*)(Al + r*SA + kq) = ral;
        }
        {
            int kp = tid>>5, n0 = (tid&31)*4;
            u32 h[4], l[4];
            split2(rb0.x, rb1.x, h[0], l[0]);
            split2(rb0.y, rb1.y, h[1], l[1]);
            split2(rb0.z, rb1.z, h[2], l[2]);
            split2(rb0.w, rb1.w, h[3], l[3]);
            *(uint4*)(Bh + kp*SB + n0) = make_uint4(h[0],h[1],h[2],h[3]);
            *(uint4*)(Bl + kp*SB + n0) = make_uint4(l[0],l[1],l[2],l[3]);
        }
    };

    ldg(0); sts(); __syncthreads();

    for (int k0=0; k0<C_DIM; k0+=32) {
        if (k0+32 < C_DIM) ldg(k0+32);   // prefetch next tile into registers

        #pragma unroll
        for (int kc=0;kc<2;kc++){
            u32 ah[2][4], al[2][4];
            #pragma unroll
            for (int mt=0;mt<2;mt++){
                int r = wm + mt*16 + (lane&7) + ((lane>>3)&1)*8;
                int cc = kc*16 + (lane>>4)*8;
                ldm4(ah[mt], Ah + r*SA + cc);
                ldm4(al[mt], Al + r*SA + cc);
            }
            #pragma unroll
            for (int nt=0;nt<4;nt++){
                int bi = (8*kc+c)*SB + wn + nt*8 + g;
                u32 bh0 = Bh[bi], bh1 = Bh[bi+4*SB];
                u32 bl0 = Bl[bi], bl1 = Bl[bi+4*SB];
                #pragma unroll
                for (int mt=0;mt<2;mt++){
                    mma_bf16(acc[mt][nt], ah[mt], bh0, bh1);
                    mma_bf16(acc[mt][nt], ah[mt], bl0, bl1);
                    mma_bf16(acc[mt][nt], al[mt], bh0, bh1);
                }
            }
        }
        __syncthreads();
        if (k0+32 < C_DIM){ sts(); __syncthreads(); }
    }

    #pragma unroll
    for (int mt=0;mt<2;mt++){
        int rg = row0 + wm + mt*16 + g;
        #pragma unroll
        for (int nt=0;nt<4;nt++){
            int jc = col0 + wn + nt*8 + 2*c;
            float bv0 = bias[jc], bv1 = bias[jc+1];
            float v00 = acc[mt][nt][0]+bv0, v01 = acc[mt][nt][1]+bv1;
            float v10 = acc[mt][nt][2]+bv0, v11 = acc[mt][nt][3]+bv1;
            if (MODE==0) {
                int part = jc>>10, cc2 = jc&1023, h = cc2>>6, d = cc2&63;
                if (part==0){ v00*=0.125f; v01*=0.125f; v10*=0.125f; v11*=0.125f; }
                bf16 *ph = (part==0)?g_qh:(part==1)?g_kh:g_vh;
                bf16 *pl = (part==0)?g_ql:(part==1)?g_kl:g_vl;
                int rr[2] = {rg, rg+8};
                float va[2][2] = {{v00,v01},{v10,v11}};
                #pragma unroll
                for (int ii=0;ii<2;ii++){
                    int t = rr[ii]&2047, bb = rr[ii]>>11;
                    size_t idx = (((size_t)(bb*NH+h))*T_SEQ + t)*HD + d;
                    u32 hi, lo; split2(va[ii][0], va[ii][1], hi, lo);
                    *(u32*)(ph+idx) = hi; *(u32*)(pl+idx) = lo;
                }
            } else {
                *(float2*)(outp + (size_t)rg*C_DIM + jc)     = make_float2(v00,v01);
                *(float2*)(outp + (size_t)(rg+8)*C_DIM + jc) = make_float2(v10,v11);
            }
        }
    }
}

// ---------------------------------------------------------------------------
// Flash attention, bf16x3 mma (identical to the passing round-6 version).
// ---------------------------------------------------------------------------
#define SK 36

__global__ __launch_bounds__(256) void attn_kernel()
{
    __shared__ u32 Kph[64*SK], Kpl[64*SK], Vph[64*SK], Vpl[64*SK];

    int tid = threadIdx.x, lane = tid&31, wid = tid>>5;
    int g = lane>>2, c = lane&3;
    int qt = blockIdx.x, bh = blockIdx.y;
    int b = bh>>4, h = bh&15;
    size_t base = (size_t)bh * T_SEQ * HD;
    int Q0 = qt*128, wrow = wid*16;

    u32 qh[4][4], ql[4][4];
    #pragma unroll
    for (int kc=0;kc<4;kc++){
        size_t i00 = base + (size_t)(Q0+wrow+g)*HD + kc*16 + 2*c;
        size_t i10 = i00 + 8ull*HD;
        qh[kc][0] = *(const u32*)(g_qh+i00); qh[kc][1] = *(const u32*)(g_qh+i10);
        qh[kc][2] = *(const u32*)(g_qh+i00+8); qh[kc][3] = *(const u32*)(g_qh+i10+8);
        ql[kc][0] = *(const u32*)(g_ql+i00); ql[kc][1] = *(const u32*)(g_ql+i10);
        ql[kc][2] = *(const u32*)(g_ql+i00+8); ql[kc][3] = *(const u32*)(g_ql+i10+8);
    }

    float m0=-1e30f, m1=-1e30f, l0=0.f, l1=0.f;
    float o[8][4];
    #pragma unroll
    for (int i=0;i<8;i++){ o[i][0]=0.f; o[i][1]=0.f; o[i][2]=0.f; o[i][3]=0.f; }

    for (int kt=0; kt<=2*qt+1; kt++){
        int K0 = kt*64;
        {
            int key = tid>>2, q4 = tid&3;
            size_t go = base + (size_t)(K0+key)*HD + q4*16;
            *(uint4*)(Kph + key*SK + q4*8)     = *(const uint4*)(g_kh+go);
            *(uint4*)(Kph + key*SK + q4*8 + 4) = *(const uint4*)(g_kh+go+8);
            *(uint4*)(Kpl + key*SK + q4*8)     = *(const uint4*)(g_kl+go);
            *(uint4*)(Kpl + key*SK + q4*8 + 4) = *(const uint4*)(g_kl+go+8);
        }
        {
            int kp = tid>>3, dd = (tid&7)*8;
            size_t r0o = base + (size_t)(K0+2*kp)*HD + dd;
            const u32* ah = (const u32*)(g_vh + r0o);
            const u32* bh2 = (const u32*)(g_vh + r0o + HD);
            const u32* al = (const u32*)(g_vl + r0o);
            const u32* bl2 = (const u32*)(g_vl + r0o + HD);
            #pragma unroll
            for (int j=0;j<4;j++){
                u32 x = ah[j], y = bh2[j];
                Vph[(dd+2*j)*SK + kp]   = prmt(x,y,0x5410);
                Vph[(dd+2*j+1)*SK + kp] = prmt(x,y,0x7632);
                x = al[j]; y = bl2[j];
                Vpl[(dd+2*j)*SK + kp]   = prmt(x,y,0x5410);
                Vpl[(dd+2*j+1)*SK + kp] = prmt(x,y,0x7632);
            }
        }
        __syncthreads();

        float s[8][4];
        #pragma unroll
        for (int i=0;i<8;i++){ s[i][0]=0.f; s[i][1]=0.f; s[i][2]=0.f; s[i][3]=0.f; }
        #pragma unroll
        for (int kc=0;kc<4;kc++){
            #pragma unroll
            for (int nt=0;nt<8;nt++){
                int bi = (nt*8+g)*SK + kc*8 + c;
                u32 bh0 = Kph[bi], bh1 = Kph[bi+4];
                u32 bl0 = Kpl[bi], bl1 = Kpl[bi+4];
                mma_bf16(s[nt], qh[kc], bh0, bh1);
                mma_bf16(s[nt], qh[kc], bl0, bl1);
                mma_bf16(s[nt], ql[kc], bh0, bh1);
            }
        }

        if (kt >= 2*qt){
            int r0 = Q0+wrow+g, r1 = r0+8;
            #pragma unroll
            for (int nt=0;nt<8;nt++){
                int kk = K0 + nt*8 + 2*c;
                if (kk   > r0) s[nt][0] = -1e30f;
                if (kk+1 > r0) s[nt][1] = -1e30f;
                if (kk   > r1) s[nt][2] = -1e30f;
                if (kk+1 > r1) s[nt][3] = -1e30f;
            }
        }

        float tm0=-1e30f, tm1=-1e30f;
        #pragma unroll
        for (int nt=0;nt<8;nt++){
            tm0 = fmaxf(tm0, fmaxf(s[nt][0], s[nt][1]));
            tm1 = fmaxf(tm1, fmaxf(s[nt][2], s[nt][3]));
        }
        tm0 = fmaxf(tm0, __shfl_xor_sync(0xffffffffu, tm0, 1));
        tm0 = fmaxf(tm0, __shfl_xor_sync(0xffffffffu, tm0, 2));
        tm1 = fmaxf(tm1, __shfl_xor_sync(0xffffffffu, tm1, 1));
        tm1 = fmaxf(tm1, __shfl_xor_sync(0xffffffffu, tm1, 2));
        float nm0 = fmaxf(m0, tm0), nm1 = fmaxf(m1, tm1);
        float cor0 = __expf(m0-nm0), cor1 = __expf(m1-nm1);
        m0 = nm0; m1 = nm1;
        float ts0 = 0.f, ts1 = 0.f;
        #pragma unroll
        for (int nt=0;nt<8;nt++){
            s[nt][0] = __expf(s[nt][0]-nm0); ts0 += s[nt][0];
            s[nt][1] = __expf(s[nt][1]-nm0); ts0 += s[nt][1];
            s[nt][2] = __expf(s[nt][2]-nm1); ts1 += s[nt][2];
            s[nt][3] = __expf(s[nt][3]-nm1); ts1 += s[nt][3];
        }
        ts0 += __shfl_xor_sync(0xffffffffu, ts0, 1);
        ts0 += __shfl_xor_sync(0xffffffffu, ts0, 2);
        ts1 += __shfl_xor_sync(0xffffffffu, ts1, 1);
        ts1 += __shfl_xor_sync(0xffffffffu, ts1, 2);
        l0 = l0*cor0 + ts0; l1 = l1*cor1 + ts1;
        #pragma unroll
        for (int dt=0;dt<8;dt++){
            o[dt][0]*=cor0; o[dt][1]*=cor0; o[dt][2]*=cor1; o[dt][3]*=cor1;
        }

        #pragma unroll
        for (int kc=0;kc<4;kc++){
            u32 ph_[4], pl_[4];
            split2(s[2*kc][0],   s[2*kc][1],   ph_[0], pl_[0]);
            split2(s[2*kc][2],   s[2*kc][3],   ph_[1], pl_[1]);
            split2(s[2*kc+1][0], s[2*kc+1][1], ph_[2], pl_[2]);
            split2(s[2*kc+1][2], s[2*kc+1][3], ph_[3], pl_[3]);
            #pragma unroll
            for (int dt=0;dt<8;dt++){
                int bi = (dt*8+g)*SK + kc*8 + c;
                u32 vh0 = Vph[bi], vh1 = Vph[bi+4];
                u32 vl0 = Vpl[bi], vl1 = Vpl[bi+4];
                mma_bf16(o[dt], ph_, vh0, vh1);
                mma_bf16(o[dt], ph_, vl0, vl1);
                mma_bf16(o[dt], pl_, vh0, vh1);
            }
        }
        __syncthreads();
    }

    float i0 = 1.f/l0, i1 = 1.f/l1;
    size_t yb0 = ((size_t)(b*T_SEQ) + Q0+wrow+g)*C_DIM + h*HD;
    size_t yb1 = yb0 + 8ull*C_DIM;
    #pragma unroll
    for (int dt=0;dt<8;dt++){
        int dc = dt*8 + 2*c;
        u32 hi, lo;
        split2(o[dt][0]*i0, o[dt][1]*i0, hi, lo);
        *(u32*)(g_yh+yb0+dc) = hi; *(u32*)(g_yl+yb0+dc) = lo;
        split2(o[dt][2]*i1, o[dt][3]*i1, hi, lo);
        *(u32*)(g_yh+yb1+dc) = hi; *(u32*)(g_yl+yb1+dc) = lo;
    }
}

// ---------------------------------------------------------------------------
extern "C" void kernel_launch(void* const* d_in, const int* in_sizes, int n_in,
                              void* d_out, int out_size)
{
    (void)in_sizes; (void)n_in; (void)out_size;
    const float* x     = (const float*)d_in[0];
    const float* W_qkv = (const float*)d_in[2];
    const float* b_qkv = (const float*)d_in[3];
    const float* W_out = (const float*)d_in[4];
    const float* b_out = (const float*)d_in[5];
    float* out = (float*)d_out;

    gemm_kernel<0><<<dim3(N_QKV/128, 4096/128), 512>>>(x, W_qkv, b_qkv, nullptr);
    attn_kernel<<<dim3(T_SEQ/128, B_SZ*NH), 256>>>();
    gemm_kernel<1><<<dim3(C_DIM/128, 4096/128), 512>>>(nullptr, W_out, b_out, out);
}